// round 1
// baseline (speedup 1.0000x reference)
#include <cuda_runtime.h>

// Problem shape (fixed for this problem instance)
#define BB 4
#define NN 32768
#define CC 128
#define DD 32
#define VV (DD * DD * DD)   // 32768

// Scratch: channel-last transposed features, (B, V, C). 67 MB device global.
__device__ float g_trans[(size_t)BB * VV * CC];

// ---------------------------------------------------------------------------
// Kernel 1: transpose (B, C, V) -> (B, V, C)
// 32x32 tiles via shared memory; coalesced reads along V, coalesced writes
// along C.
// ---------------------------------------------------------------------------
__global__ __launch_bounds__(256)
void transpose_k(const float* __restrict__ in) {
    __shared__ float tile[32][33];
    const int b  = blockIdx.z;
    const int v0 = blockIdx.x * 32;
    const int c0 = blockIdx.y * 32;
    const int x  = threadIdx.x;   // 0..31
    const int y  = threadIdx.y;   // 0..7

    #pragma unroll
    for (int j = 0; j < 4; j++) {
        const int i = y + j * 8;  // channel within tile
        tile[i][x] = in[((size_t)b * CC + (c0 + i)) * VV + (v0 + x)];
    }
    __syncthreads();
    #pragma unroll
    for (int j = 0; j < 4; j++) {
        const int i = y + j * 8;  // voxel within tile
        g_trans[((size_t)b * VV + (v0 + i)) * CC + (c0 + x)] = tile[x][i];
    }
}

// ---------------------------------------------------------------------------
// Kernel 2: per-point trilinear-corner gather.
// One block (256 threads) per point. Warp k (0..7) handles corner
// (dx,dy,dz) = (k>>2 & 1, k>>1 & 1, k & 1). Each lane moves 4 channels as one
// float4: LDG.128 from g_trans (contiguous 512B per warp, L2-resident) and
// STG.128 to out (contiguous 4KB per block). Streaming store hint keeps the
// output write stream from evicting features out of L2.
// ---------------------------------------------------------------------------
__global__ __launch_bounds__(256)
void sample_k(const float* __restrict__ pt, float* __restrict__ out) {
    const int bn   = blockIdx.x;          // 0 .. B*N-1
    const int b    = bn >> 15;            // N = 32768
    const int tid  = threadIdx.x;
    const int k    = tid >> 5;            // corner id = warp id
    const int lane = tid & 31;

    const float scale = (DD - 1) * 0.5f;  // 15.5
    const float px = (__ldg(&pt[(size_t)3 * bn + 0]) + 1.0f) * scale;
    const float py = (__ldg(&pt[(size_t)3 * bn + 1]) + 1.0f) * scale;
    const float pz = (__ldg(&pt[(size_t)3 * bn + 2]) + 1.0f) * scale;

    const int ix = (int)floorf(px) + ((k >> 2) & 1);
    const int iy = (int)floorf(py) + ((k >> 1) & 1);
    const int iz = (int)floorf(pz) + (k & 1);

    const bool valid = ((unsigned)ix < DD) & ((unsigned)iy < DD) & ((unsigned)iz < DD);

    float4 v = make_float4(0.0f, 0.0f, 0.0f, 0.0f);
    if (valid) {
        const int flat = (ix * DD + iy) * DD + iz;
        const float4* src =
            (const float4*)(g_trans + ((size_t)b * VV + flat) * CC) + lane;
        v = __ldg(src);
    }

    float4* dst = (float4*)(out + ((size_t)bn * 8 + k) * CC) + lane;
    __stcs(dst, v);
}

// ---------------------------------------------------------------------------
// Launch
// ---------------------------------------------------------------------------
extern "C" void kernel_launch(void* const* d_in, const int* in_sizes, int n_in,
                              void* d_out, int out_size) {
    const float* ptcloud = (const float*)d_in[0];  // (B, N, 3)
    const float* feats   = (const float*)d_in[1];  // (B, C, D, D, D)
    float* out           = (float*)d_out;          // (B, N, 8, C)

    dim3 tgrid(VV / 32, CC / 32, BB);   // (1024, 4, 4)
    transpose_k<<<tgrid, dim3(32, 8)>>>(feats);

    sample_k<<<BB * NN, 256>>>(ptcloud, out);
}

// round 2
// speedup vs baseline: 1.4317x; 1.4317x over previous
#include <cuda_runtime.h>

// Problem shape (fixed for this problem instance)
#define BB 4
#define NN 32768
#define CC 128
#define DD 32
#define VV (DD * DD * DD)   // 32768

// Scratch: channel-last transposed features, (B, V, C). 64 MB device global.
__device__ float g_trans[(size_t)BB * VV * CC];

// ---------------------------------------------------------------------------
// Kernel 1: transpose (B, C, V) -> (B, V, C), float4 on both sides.
// 32x32 float tile in shared memory, [32][33] padding -> conflict-free for
// both the STS (read phase) and LDS (write phase) access patterns.
// ---------------------------------------------------------------------------
__global__ __launch_bounds__(256)
void transpose_k(const float* __restrict__ in) {
    __shared__ float tile[32][33];
    const int b   = blockIdx.z;
    const int v0  = blockIdx.x * 32;
    const int c0  = blockIdx.y * 32;
    const int tid = threadIdx.x;

    // Read phase: thread -> (channel row c_i, voxel float4 v4)
    {
        const int c_i = tid >> 3;        // 0..31
        const int v4  = tid & 7;         // 0..7
        const float4 f = *(const float4*)
            (in + ((size_t)b * CC + (c0 + c_i)) * VV + (v0 + 4 * v4));
        tile[c_i][4 * v4 + 0] = f.x;
        tile[c_i][4 * v4 + 1] = f.y;
        tile[c_i][4 * v4 + 2] = f.z;
        tile[c_i][4 * v4 + 3] = f.w;
    }
    __syncthreads();
    // Write phase: thread -> (voxel row v_i, channel float4 c4)
    {
        const int v_i = tid >> 3;        // 0..31
        const int c4  = tid & 7;         // 0..7
        float4 g;
        g.x = tile[4 * c4 + 0][v_i];
        g.y = tile[4 * c4 + 1][v_i];
        g.z = tile[4 * c4 + 2][v_i];
        g.w = tile[4 * c4 + 3][v_i];
        *(float4*)(g_trans + ((size_t)b * VV + (v0 + v_i)) * CC + (c0 + 4 * c4)) = g;
    }
}

// ---------------------------------------------------------------------------
// Kernel 2: per-point trilinear-corner gather, one WARP per point.
// Lane = one 16B channel chunk (4 channels). The warp issues 8 independent
// predicated LDG.128s (one per corner) -> MLP=8 per thread, then 8 coalesced
// STG.128s covering 4KB contiguous output per warp. Streaming store hint
// keeps g_trans resident in L2 against the 536MB output write stream.
// ---------------------------------------------------------------------------
__global__ __launch_bounds__(256)
void sample_k(const float* __restrict__ pt, float* __restrict__ out) {
    const int bn   = blockIdx.x * 8 + (threadIdx.x >> 5);  // point id, 0..B*N-1
    const int b    = bn >> 15;                             // N = 32768
    const int lane = threadIdx.x & 31;

    const float scale = (DD - 1) * 0.5f;  // 15.5
    const float px = (__ldg(&pt[(size_t)3 * bn + 0]) + 1.0f) * scale;
    const float py = (__ldg(&pt[(size_t)3 * bn + 1]) + 1.0f) * scale;
    const float pz = (__ldg(&pt[(size_t)3 * bn + 2]) + 1.0f) * scale;

    const int lx = (int)floorf(px);
    const int ly = (int)floorf(py);
    const int lz = (int)floorf(pz);

    const float* base = g_trans + (size_t)b * VV * CC;

    float4 v[8];
    #pragma unroll
    for (int k = 0; k < 8; k++) {
        const int ix = lx + ((k >> 2) & 1);
        const int iy = ly + ((k >> 1) & 1);
        const int iz = lz + (k & 1);
        const bool valid =
            ((unsigned)ix < DD) & ((unsigned)iy < DD) & ((unsigned)iz < DD);
        v[k] = make_float4(0.0f, 0.0f, 0.0f, 0.0f);
        if (valid) {
            const int flat = (ix * DD + iy) * DD + iz;
            v[k] = __ldg((const float4*)(base + (size_t)flat * CC) + lane);
        }
    }

    float4* dst = (float4*)(out + (size_t)bn * 8 * CC) + lane;
    #pragma unroll
    for (int k = 0; k < 8; k++)
        __stcs(dst + (size_t)k * 32, v[k]);
}

// ---------------------------------------------------------------------------
// Launch
// ---------------------------------------------------------------------------
extern "C" void kernel_launch(void* const* d_in, const int* in_sizes, int n_in,
                              void* d_out, int out_size) {
    const float* ptcloud = (const float*)d_in[0];  // (B, N, 3)
    const float* feats   = (const float*)d_in[1];  // (B, C, D, D, D)
    float* out           = (float*)d_out;          // (B, N, 8, C)

    dim3 tgrid(VV / 32, CC / 32, BB);   // (1024, 4, 4)
    transpose_k<<<tgrid, dim3(256)>>>(feats);

    sample_k<<<(BB * NN) / 8, 256>>>(ptcloud, out);
}

// round 3
// speedup vs baseline: 1.4906x; 1.0412x over previous
#include <cuda_runtime.h>

// Problem shape (fixed for this problem instance)
#define BB 4
#define NN 32768
#define CC 128
#define DD 32
#define VV (DD * DD * DD)   // 32768

// Scratch: channel-last transposed features, (B, V, C). 64 MB device global.
__device__ float g_trans[(size_t)BB * VV * CC];

// ---------------------------------------------------------------------------
// Kernel 1: transpose (B, C, V) -> (B, V, C), float4 both sides, MLP=4.
// One block handles a 128-channel x 32-voxel slab through a [128][33] smem
// tile (16.9 KB). Each thread: 4 independent LDG.128 + 4 independent STG.128.
// ---------------------------------------------------------------------------
__global__ __launch_bounds__(256)
void transpose_k(const float* __restrict__ in) {
    __shared__ float tile[128][33];
    const int b   = blockIdx.y;
    const int v0  = blockIdx.x * 32;
    const int tid = threadIdx.x;

    // Read phase: 4 x (channel row c_i, voxel float4 v4)
    {
        const int v4 = tid & 7;                 // 0..7 -> voxel float4
        float4 f[4];
        #pragma unroll
        for (int j = 0; j < 4; j++) {
            const int c_i = 32 * j + (tid >> 3);  // 0..127
            f[j] = *(const float4*)
                (in + ((size_t)b * CC + c_i) * VV + (v0 + 4 * v4));
        }
        #pragma unroll
        for (int j = 0; j < 4; j++) {
            const int c_i = 32 * j + (tid >> 3);
            tile[c_i][4 * v4 + 0] = f[j].x;
            tile[c_i][4 * v4 + 1] = f[j].y;
            tile[c_i][4 * v4 + 2] = f[j].z;
            tile[c_i][4 * v4 + 3] = f[j].w;
        }
    }
    __syncthreads();
    // Write phase: 4 x (voxel row v_i, channel float4 c4)
    {
        const int v_i = tid >> 3;               // 0..31
        #pragma unroll
        for (int j = 0; j < 4; j++) {
            const int c4 = (tid & 7) + 8 * j;   // 0..31 -> channel float4
            float4 g;
            g.x = tile[4 * c4 + 0][v_i];
            g.y = tile[4 * c4 + 1][v_i];
            g.z = tile[4 * c4 + 2][v_i];
            g.w = tile[4 * c4 + 3][v_i];
            *(float4*)(g_trans + ((size_t)b * VV + (v0 + v_i)) * CC + 4 * c4) = g;
        }
    }
}

// ---------------------------------------------------------------------------
// Kernel 2: per-point trilinear-corner gather, TWO points per warp.
// Lane = one 16B channel chunk (4 channels). The warp issues 16 independent
// predicated LDG.128s (8 corners x 2 points) -> MLP=16 per thread, then 16
// coalesced STG.128s covering 8KB contiguous output per warp. Streaming
// store hint keeps g_trans resident in L2 against the output write stream.
// ---------------------------------------------------------------------------
__global__ __launch_bounds__(256)
void sample_k(const float* __restrict__ pt, float* __restrict__ out) {
    const int warp = blockIdx.x * 8 + (threadIdx.x >> 5);
    const int bn0  = warp * 2;                 // first point id
    const int lane = threadIdx.x & 31;

    const float scale = (DD - 1) * 0.5f;       // 15.5

    float4 v[16];

    #pragma unroll
    for (int p = 0; p < 2; p++) {
        const int bn = bn0 + p;
        const int b  = bn >> 15;               // N = 32768
        const float px = (__ldg(&pt[(size_t)3 * bn + 0]) + 1.0f) * scale;
        const float py = (__ldg(&pt[(size_t)3 * bn + 1]) + 1.0f) * scale;
        const float pz = (__ldg(&pt[(size_t)3 * bn + 2]) + 1.0f) * scale;
        const int lx = (int)floorf(px);
        const int ly = (int)floorf(py);
        const int lz = (int)floorf(pz);

        const float* base = g_trans + (size_t)b * VV * CC;

        #pragma unroll
        for (int k = 0; k < 8; k++) {
            const int ix = lx + ((k >> 2) & 1);
            const int iy = ly + ((k >> 1) & 1);
            const int iz = lz + (k & 1);
            const bool valid =
                ((unsigned)ix < DD) & ((unsigned)iy < DD) & ((unsigned)iz < DD);
            v[p * 8 + k] = make_float4(0.0f, 0.0f, 0.0f, 0.0f);
            if (valid) {
                const int flat = (ix * DD + iy) * DD + iz;
                v[p * 8 + k] = __ldg((const float4*)(base + (size_t)flat * CC) + lane);
            }
        }
    }

    float4* dst = (float4*)(out + (size_t)bn0 * 8 * CC) + lane;
    #pragma unroll
    for (int k = 0; k < 16; k++)
        __stcs(dst + (size_t)k * 32, v[k]);
}

// ---------------------------------------------------------------------------
// Launch
// ---------------------------------------------------------------------------
extern "C" void kernel_launch(void* const* d_in, const int* in_sizes, int n_in,
                              void* d_out, int out_size) {
    const float* ptcloud = (const float*)d_in[0];  // (B, N, 3)
    const float* feats   = (const float*)d_in[1];  // (B, C, D, D, D)
    float* out           = (float*)d_out;          // (B, N, 8, C)

    dim3 tgrid(VV / 32, BB);            // (1024, 4)
    transpose_k<<<tgrid, 256>>>(feats);

    sample_k<<<(BB * NN) / 16, 256>>>(ptcloud, out);
}